// round 12
// baseline (speedup 1.0000x reference)
#include <cuda_runtime.h>
#include <math.h>
#include <stdint.h>

#define BB 512
#define NN 64
#define EE 512
#define AA 16
#define ITERS 8

#define THREADS 1024
#define CHUNK_TILES 32
#define CHUNK_BYTES (CHUNK_TILES * 1024)      // 32 KB
#define NCHUNK_IT   16                        // chunks per iteration (512 tiles)
#define STREAM_LEN  (ITERS * 8)               // chunks per half over whole kernel
// SMEM: staging 128K + mf 32K + mb 32K + q 4K + nv 4K + idx/csr ~10K
#define SMEM_BYTES (212 * 1024)

// ---------------- mbarrier / bulk-copy helpers ------------------------------
__device__ __forceinline__ uint32_t s2u(const void* p) {
    uint32_t a;
    asm("{ .reg .u64 t; cvta.to.shared.u64 t, %1; cvt.u32.u64 %0, t; }"
        : "=r"(a) : "l"(p));
    return a;
}
__device__ __forceinline__ void mbar_init(uint32_t a, uint32_t cnt) {
    asm volatile("mbarrier.init.shared.b64 [%0], %1;" :: "r"(a), "r"(cnt) : "memory");
}
__device__ __forceinline__ void mbar_expect_tx(uint32_t a, uint32_t bytes) {
    asm volatile("mbarrier.arrive.expect_tx.shared.b64 _, [%0], %1;"
                 :: "r"(a), "r"(bytes) : "memory");
}
__device__ __forceinline__ void mbar_arrive(uint32_t a) {
    asm volatile("mbarrier.arrive.shared.b64 _, [%0];" :: "r"(a) : "memory");
}
__device__ __forceinline__ void mbar_wait(uint32_t a, uint32_t parity) {
    asm volatile(
        "{\n\t.reg .pred P;\n\t"
        "WL_%=:\n\t"
        "mbarrier.try_wait.parity.acquire.cta.shared::cta.b64 P, [%0], %1, 0x989680;\n\t"
        "@P bra.uni WD_%=;\n\t"
        "bra.uni WL_%=;\n\t"
        "WD_%=:\n\t}"
        :: "r"(a), "r"(parity) : "memory");
}
__device__ __forceinline__ void bulk_g2s(uint32_t dst, const void* src,
                                         uint32_t bytes, uint32_t mbar) {
    asm volatile(
        "cp.async.bulk.shared::cta.global.mbarrier::complete_tx::bytes [%0], [%1], %2, [%3];"
        :: "r"(dst), "l"(src), "r"(bytes), "r"(mbar) : "memory");
}

// ---------------- fused persistent kernel: one CTA per batch ----------------
__global__ void __launch_bounds__(THREADS, 1) k_main(
    const float* __restrict__ node_vals,
    const float* __restrict__ edge_vals,
    const int* __restrict__ ef_g,
    const int* __restrict__ et_g,
    float* __restrict__ out, int out_size)
{
    extern __shared__ float smem[];
    float* s_stage = smem;                       // 32768 floats (128 KB): h0s0,h0s1,h1s0,h1s1
    float* s_mf  = s_stage + 4 * (CHUNK_BYTES / 4);
    float* s_mb  = s_mf + EE * AA;
    float* s_q   = s_mb + EE * AA;
    float* s_nv  = s_q  + NN * AA;
    int*   s_ef  = (int*)(s_nv + NN * AA);
    int*   s_et  = s_ef + EE;
    int*   s_ino = s_et + EE;
    int*   s_out = s_ino + NN + 1;
    int*   s_inl = s_out + NN + 1;
    int*   s_onl = s_inl + EE;
    int*   s_a   = s_onl + EE;
    int*   s_am  = s_a  + NN;
    float* s_red = (float*)(s_am + NN);          // 32

    __shared__ __align__(8) unsigned long long s_bar[8]; // per half: full0,full1,empty0,empty1
    __shared__ float sh_qmax;
    __shared__ int   sh_flag;

    const int b    = blockIdx.x;
    const int tid  = threadIdx.x;                // 1024
    const int lane = tid & 31;
    const int warp = tid >> 5;                   // 0..31
    const int halfid = warp >> 4;                // 0/1
    const int wih    = warp & 15;                // warp within half
    const unsigned full = 0xffffffffu;

    const uint32_t u_stage = s2u(s_stage);
    const uint32_t u_bar   = s2u(s_bar);
    // barrier addresses for this half
    const uint32_t bF0 = u_bar + (halfid * 4 + 0) * 8;
    const uint32_t bF1 = u_bar + (halfid * 4 + 1) * 8;
    const uint32_t bE0 = u_bar + (halfid * 4 + 2) * 8;
    const uint32_t bE1 = u_bar + (halfid * 4 + 3) * 8;
    const bool is_prod = (tid == (halfid << 9)); // thread 0 and 512

    // ---------------- init: load inputs, zero messages, init barriers -------
    {
        const float* nvp = node_vals + (size_t)b * NN * AA;
        float v = nvp[tid];                      // 1024 == NN*AA
        s_nv[tid] = v;
        s_q[tid]  = v * (1.0f / NN);
        float4 z = make_float4(0.f, 0.f, 0.f, 0.f);
        #pragma unroll
        for (int p = 0; p < 4; p++)
            ((float4*)s_mf)[tid + p * THREADS] = z;   // covers s_mf then s_mb
        if (tid < EE)            s_ef[tid] = ef_g[tid];
        else                     s_et[tid - EE] = et_g[tid - EE];
        if (tid == 0) {
            sh_qmax = -INFINITY; sh_flag = 0;
            #pragma unroll
            for (int h = 0; h < 2; h++) {
                mbar_init(u_bar + (h * 4 + 0) * 8, 1);   // full: 1 expect_tx arrive
                mbar_init(u_bar + (h * 4 + 1) * 8, 1);
                mbar_init(u_bar + (h * 4 + 2) * 8, 16);  // empty: 16 warp arrivals
                mbar_init(u_bar + (h * 4 + 3) * 8, 16);
            }
            asm volatile("fence.proxy.async.shared::cta;" ::: "memory");
        }

        // initial per-node argmax over RAW node_vals
        int a = tid & 15;
        float bv = v; int bi = a;
        #pragma unroll
        for (int m = 1; m < 16; m <<= 1) {
            float ov = __shfl_xor_sync(full, bv, m, 16);
            int   oi = __shfl_xor_sync(full, bi, m, 16);
            if (ov > bv || (ov == bv && oi < bi)) { bv = ov; bi = oi; }
        }
        if (a == 0) s_a[tid >> 4] = bi;
    }
    __syncthreads();

    // ---------------- prime the DMA ring (2 chunks per half) ----------------
    if (is_prod) {
        #pragma unroll
        for (int g = 0; g < 2; g++) {
            int cit = (g << 1) + halfid;         // iteration-local chunk id
            uint32_t fb = (g == 0) ? bF0 : bF1;
            mbar_expect_tx(fb, CHUNK_BYTES);
            bulk_g2s(u_stage + (halfid * 2 + g) * CHUNK_BYTES,
                     edge_vals + (((size_t)b * EE + cit * CHUNK_TILES) << 8),
                     CHUNK_BYTES, fb);
        }
    }

    // ---------------- CSR adjacency build (deterministic, ascending e) ------
    {
        if (tid < NN) {
            int c = 0;
            for (int e = 0; e < EE; e++) if (s_et[e] == tid) c++;
            s_ino[tid + 1] = c;
        } else if (tid < 2 * NN) {
            int n = tid - NN; int c = 0;
            for (int e = 0; e < EE; e++) if (s_ef[e] == n) c++;
            s_out[n + 1] = c;
        }
        __syncthreads();
        if (tid == 0) {
            s_ino[0] = 0; s_out[0] = 0;
            for (int n = 0; n < NN; n++) {
                s_ino[n + 1] += s_ino[n];
                s_out[n + 1] += s_out[n];
            }
        }
        __syncthreads();
        if (tid < NN) {
            int c = s_ino[tid];
            for (int e = 0; e < EE; e++) if (s_et[e] == tid) s_inl[c++] = e;
        } else if (tid < 2 * NN) {
            int n = tid - NN; int c = s_out[n];
            for (int e = 0; e < EE; e++) if (s_ef[e] == n) s_onl[c++] = e;
        }
    }
    __syncthreads();

    // ---------------- eval helper ----------------
    auto do_eval = [&]() {
        float contrib = 0.f;
        if (tid < NN)
            contrib += s_nv[tid * AA + s_a[tid]] * (1.0f / NN);
        if (tid < EE) {
            int e  = tid;
            int af = s_a[s_ef[e]];
            int at = s_a[s_et[e]];
            contrib += __ldg(&edge_vals[(((size_t)b * EE + e) * AA + af) * AA + at])
                       * (1.0f / EE);
        }
        #pragma unroll
        for (int m = 16; m > 0; m >>= 1)
            contrib += __shfl_xor_sync(full, contrib, m);
        if (lane == 0) s_red[warp] = contrib;
        __syncthreads();
        if (warp == 0) {
            float v = s_red[lane];
            #pragma unroll
            for (int m = 16; m > 0; m >>= 1)
                v += __shfl_xor_sync(full, v, m);
            if (lane == 0) {
                if (v > sh_qmax) { sh_qmax = v; sh_flag = 1; }
                else             { sh_flag = 0; }
            }
        }
        __syncthreads();
        if (sh_flag && tid < NN) s_am[tid] = s_a[tid];
        __syncthreads();
    };

    do_eval();   // iteration-0 eval of raw argmax assignment

    const int tsel = lane >> 4;      // which of the 2 tiles in this warp's pair
    const int tl   = lane & 15;
    const int rg   = tl >> 2;        // row group: rows 4*rg .. 4*rg+3
    const int kg   = tl & 3;         // col group: cols 4*kg .. 4*kg+3
    const int tin  = (wih << 1) + tsel;               // tile index within chunk
    const float* stage_t0 = s_stage + (halfid * 2 + 0) * (CHUNK_BYTES / 4) + tin * 256;
    const float* stage_t1 = s_stage + (halfid * 2 + 1) * (CHUNK_BYTES / 4) + tin * 256;

    // ---------------- 8 message-passing iterations ----------------
    for (int it = 0; it < ITERS; it++) {
        // ---- message phase: chunked DMA pipeline; 4x4 blocks per lane ----
        {
            const float sc = 1.0f / EE;
            #pragma unroll 1
            for (int j = 0; j < 8; j++) {
                int g    = (it << 3) + j;        // stream index for this half
                int slot = g & 1;
                int par  = (g >> 1) & 1;
                int cit  = (j << 1) + halfid;    // iteration-local chunk id
                uint32_t fb = slot ? bF1 : bF0;
                uint32_t eb = slot ? bE1 : bE0;

                mbar_wait(fb, par);              // chunk data ready in staging

                int e = (cit << 5) + tin;        // global edge id of my tile
                const float4* tile4 =
                    (const float4*)(slot ? stage_t1 : stage_t0);
                int nf = s_ef[e], nt = s_et[e];
                float* mfp = s_mf + (e << 4);
                float* mbp = s_mb + (e << 4);

                // d[at] = q[to][at] - mf_old[at]   (this lane's 4 cols, group kg)
                float4 qt4  = ((const float4*)(s_q + (nt << 4)))[kg];
                float4 mfo4 = ((const float4*)mfp)[kg];
                float4 d4 = make_float4(qt4.x - mfo4.x, qt4.y - mfo4.y,
                                        qt4.z - mfo4.z, qt4.w - mfo4.w);
                // c[af] = q[from][af] - mb_old[af] (this lane's 4 rows, group rg)
                float4 qf4  = ((const float4*)(s_q + (nf << 4)))[rg];
                float4 mbo4 = ((const float4*)mbp)[rg];
                float4 c4 = make_float4(qf4.x - mbo4.x, qf4.y - mbo4.y,
                                        qf4.z - mbo4.z, qf4.w - mbo4.w);

                float4 f4, m4, v;
                int base = (rg << 4) + kg;

                // j = 0 : row 4rg+0
                v = tile4[base];
                v.x *= sc; v.y *= sc; v.z *= sc; v.w *= sc;
                m4.x = fmaxf(fmaxf(d4.x + v.x, d4.y + v.y),
                             fmaxf(d4.z + v.z, d4.w + v.w));
                f4.x = c4.x + v.x; f4.y = c4.x + v.y;
                f4.z = c4.x + v.z; f4.w = c4.x + v.w;
                // row 4rg+1
                v = tile4[base + 4];
                v.x *= sc; v.y *= sc; v.z *= sc; v.w *= sc;
                m4.y = fmaxf(fmaxf(d4.x + v.x, d4.y + v.y),
                             fmaxf(d4.z + v.z, d4.w + v.w));
                f4.x = fmaxf(f4.x, c4.y + v.x); f4.y = fmaxf(f4.y, c4.y + v.y);
                f4.z = fmaxf(f4.z, c4.y + v.z); f4.w = fmaxf(f4.w, c4.y + v.w);
                // row 4rg+2
                v = tile4[base + 8];
                v.x *= sc; v.y *= sc; v.z *= sc; v.w *= sc;
                m4.z = fmaxf(fmaxf(d4.x + v.x, d4.y + v.y),
                             fmaxf(d4.z + v.z, d4.w + v.w));
                f4.x = fmaxf(f4.x, c4.z + v.x); f4.y = fmaxf(f4.y, c4.z + v.y);
                f4.z = fmaxf(f4.z, c4.z + v.z); f4.w = fmaxf(f4.w, c4.z + v.w);
                // row 4rg+3
                v = tile4[base + 12];
                v.x *= sc; v.y *= sc; v.z *= sc; v.w *= sc;
                m4.w = fmaxf(fmaxf(d4.x + v.x, d4.y + v.y),
                             fmaxf(d4.z + v.z, d4.w + v.w));
                f4.x = fmaxf(f4.x, c4.w + v.x); f4.y = fmaxf(f4.y, c4.w + v.y);
                f4.z = fmaxf(f4.z, c4.w + v.z); f4.w = fmaxf(f4.w, c4.w + v.w);

                // reduce row-maxes (mb) over the 4 col-groups: xor 1, 2 (exact max)
                m4.x = fmaxf(m4.x, __shfl_xor_sync(full, m4.x, 1));
                m4.y = fmaxf(m4.y, __shfl_xor_sync(full, m4.y, 1));
                m4.z = fmaxf(m4.z, __shfl_xor_sync(full, m4.z, 1));
                m4.w = fmaxf(m4.w, __shfl_xor_sync(full, m4.w, 1));
                m4.x = fmaxf(m4.x, __shfl_xor_sync(full, m4.x, 2));
                m4.y = fmaxf(m4.y, __shfl_xor_sync(full, m4.y, 2));
                m4.z = fmaxf(m4.z, __shfl_xor_sync(full, m4.z, 2));
                m4.w = fmaxf(m4.w, __shfl_xor_sync(full, m4.w, 2));

                // reduce col-maxes (mf) over the 4 row-groups: xor 4, 8 (exact max)
                f4.x = fmaxf(f4.x, __shfl_xor_sync(full, f4.x, 4));
                f4.y = fmaxf(f4.y, __shfl_xor_sync(full, f4.y, 4));
                f4.z = fmaxf(f4.z, __shfl_xor_sync(full, f4.z, 4));
                f4.w = fmaxf(f4.w, __shfl_xor_sync(full, f4.w, 4));
                f4.x = fmaxf(f4.x, __shfl_xor_sync(full, f4.x, 8));
                f4.y = fmaxf(f4.y, __shfl_xor_sync(full, f4.y, 8));
                f4.z = fmaxf(f4.z, __shfl_xor_sync(full, f4.z, 8));
                f4.w = fmaxf(f4.w, __shfl_xor_sync(full, f4.w, 8));

                // mean-center mf over 16 'at' (serial 4 + xor1 + xor2)
                float s = f4.x + f4.y + f4.z + f4.w;
                s += __shfl_xor_sync(full, s, 1);
                s += __shfl_xor_sync(full, s, 2);
                s *= (1.0f / AA);
                f4.x -= s; f4.y -= s; f4.z -= s; f4.w -= s;

                // mean-center mb over 16 'af' — exact R6/R8 sum tree
                float4 t4;
                t4.x = m4.x + __shfl_xor_sync(full, m4.x, 8);
                t4.y = m4.y + __shfl_xor_sync(full, m4.y, 8);
                t4.z = m4.z + __shfl_xor_sync(full, m4.z, 8);
                t4.w = m4.w + __shfl_xor_sync(full, m4.w, 8);
                float sm = (t4.x + t4.y) + (t4.z + t4.w);
                sm += __shfl_xor_sync(full, sm, 4);
                sm *= (1.0f / AA);
                m4.x -= sm; m4.y -= sm; m4.z -= sm; m4.w -= sm;

                if (rg == 0) ((float4*)mfp)[kg] = f4;
                if (kg == 0) ((float4*)mbp)[rg] = m4;

                __syncwarp();
                if (lane == 0) mbar_arrive(eb);  // this warp done with the chunk

                // producer: refill this slot with chunk g+2 once all 16 warps done
                if (is_prod) {
                    int g2 = g + 2;
                    if (g2 < STREAM_LEN) {
                        mbar_wait(eb, par);      // all consumers of chunk g arrived
                        int cit2 = ((g2 & 7) << 1) + halfid;
                        mbar_expect_tx(fb, CHUNK_BYTES);
                        bulk_g2s(u_stage + (halfid * 2 + slot) * CHUNK_BYTES,
                                 edge_vals + (((size_t)b * EE + cit2 * CHUNK_TILES) << 8),
                                 CHUNK_BYTES, fb);
                    }
                }
            }
        }
        __syncthreads();

        // ---- node update + argmax (single pass: 1024 threads == NN*AA) ----
        {
            int n = tid >> 4, a = tid & 15;
            float v = s_nv[tid] * (1.0f / NN);
            int i0 = s_ino[n], i1 = s_ino[n + 1];
            for (int i = i0; i < i1; i++) v += s_mf[(s_inl[i] << 4) + a];
            int o0 = s_out[n], o1 = s_out[n + 1];
            for (int i = o0; i < o1; i++) v += s_mb[(s_onl[i] << 4) + a];
            s_q[tid] = v;

            float bv = v; int bi = a;
            #pragma unroll
            for (int m = 1; m < 16; m <<= 1) {
                float ov = __shfl_xor_sync(full, bv, m, 16);
                int   oi = __shfl_xor_sync(full, bi, m, 16);
                if (ov > bv || (ov == bv && oi < bi)) { bv = ov; bi = oi; }
            }
            if (a == 0) s_a[n] = bi;
        }
        __syncthreads();

        // ---- eval current assignment, keep best ----
        do_eval();
    }

    // ---------------- write results directly ----------------
    int tot = BB + BB * NN;
    if (out_size >= tot) {
        if (tid == 0) out[b] = sh_qmax;
        if (tid < NN) out[BB + b * NN + tid] = (float)s_am[tid];
    } else if (out_size == BB * NN) {
        if (tid < NN) out[b * NN + tid] = (float)s_am[tid];
    } else {
        if (tid == 0 && b < out_size) out[b] = sh_qmax;
    }
}

// ---------------- launch ----------------------------------------------------
extern "C" void kernel_launch(void* const* d_in, const int* in_sizes, int n_in,
                              void* d_out, int out_size) {
    const float* node_vals = (const float*)d_in[0];
    const float* edge_vals = (const float*)d_in[1];
    const int*   ef        = (const int*)d_in[2];
    const int*   et        = (const int*)d_in[3];
    float* out = (float*)d_out;

    cudaFuncSetAttribute(k_main, cudaFuncAttributeMaxDynamicSharedMemorySize,
                         SMEM_BYTES);

    k_main<<<BB, THREADS, SMEM_BYTES>>>(node_vals, edge_vals, ef, et,
                                        out, out_size);
}

// round 15
// speedup vs baseline: 1.1721x; 1.1721x over previous
#include <cuda_runtime.h>
#include <math.h>

#define BB 512
#define NN 64
#define EE 512
#define AA 16
#define ITERS 8

#define THREADS 512
#define SMEM_BYTES (84 * 1024)

// ---------------- L2 evict-last via createpolicy + cache_hint ----------------
// (pure cache hint, bit-identical data; the direct .L2::evict_last qualifier
//  is rejected by ptxas on 128-bit loads for sm_103)
__device__ __forceinline__ unsigned long long mk_policy() {
    unsigned long long p;
    asm("createpolicy.fractional.L2::evict_last.b64 %0, 1.0;" : "=l"(p));
    return p;
}
__device__ __forceinline__ float4 ldg_el4(const float4* p, unsigned long long pol) {
    float4 r;
    asm("ld.global.nc.L2::cache_hint.v4.f32 {%0,%1,%2,%3}, [%4], %5;"
        : "=f"(r.x), "=f"(r.y), "=f"(r.z), "=f"(r.w) : "l"(p), "l"(pol));
    return r;
}
__device__ __forceinline__ float ldg_el1(const float* p, unsigned long long pol) {
    float r;
    asm("ld.global.nc.L2::cache_hint.f32 %0, [%1], %2;"
        : "=f"(r) : "l"(p), "l"(pol));
    return r;
}

// ---------------- fused persistent kernel: one CTA per batch ----------------
// 512 threads, ~83KB dynamic SMEM -> 2 CTAs/SM so two batches overlap phases.
__global__ void __launch_bounds__(THREADS, 2) k_main(
    const float* __restrict__ node_vals,
    const float* __restrict__ edge_vals,
    const int* __restrict__ ef_g,
    const int* __restrict__ et_g,
    float* __restrict__ out, int out_size)
{
    extern __shared__ float smem[];
    float* s_mf  = smem;                    // 8192 floats (32 KB)
    float* s_mb  = s_mf + EE * AA;          // 8192 floats (32 KB)
    float* s_q   = s_mb + EE * AA;          // 1024 floats (4 KB)
    float* s_nv  = s_q  + NN * AA;          // 1024 floats (4 KB)
    int*   s_ef  = (int*)(s_nv + NN * AA);  // 512
    int*   s_et  = s_ef + EE;               // 512
    int*   s_ino = s_et + EE;               // 65
    int*   s_out = s_ino + NN + 1;          // 65
    int*   s_inl = s_out + NN + 1;          // 512
    int*   s_onl = s_inl + EE;              // 512
    int*   s_a   = s_onl + EE;              // 64
    int*   s_am  = s_a  + NN;               // 64
    float* s_red = (float*)(s_am + NN);     // 16

    __shared__ float sh_qmax;
    __shared__ int   sh_flag;

    const int b    = blockIdx.x;
    const int tid  = threadIdx.x;           // 512
    const int lane = tid & 31;
    const int warp = tid >> 5;              // 0..15
    const unsigned full = 0xffffffffu;
    const unsigned long long pol = mk_policy();

    // ---------------- init: load inputs, zero messages ----------------
    {
        const float* nvp = node_vals + (size_t)b * NN * AA;
        float4 z = make_float4(0.f, 0.f, 0.f, 0.f);
        #pragma unroll
        for (int p = 0; p < 2; p++) {
            int i = tid + p * THREADS;      // 0..1023
            float v = nvp[i];
            s_nv[i] = v;
            s_q[i]  = v * (1.0f / NN);
        }
        #pragma unroll
        for (int p = 0; p < 8; p++)
            ((float4*)s_mf)[tid + p * THREADS] = z;   // covers s_mf then s_mb (contiguous)
        s_ef[tid] = ef_g[tid];
        s_et[tid] = et_g[tid];
        if (tid == 0) { sh_qmax = -INFINITY; sh_flag = 0; }
    }
    __syncthreads();

    // ---------------- initial per-node argmax over RAW node_vals -------------
    {
        #pragma unroll
        for (int p = 0; p < 2; p++) {
            int n = (tid >> 4) + p * 32;
            int a = tid & 15;
            float bv = s_nv[n * AA + a]; int bi = a;
            #pragma unroll
            for (int m = 1; m < 16; m <<= 1) {
                float ov = __shfl_xor_sync(full, bv, m, 16);
                int   oi = __shfl_xor_sync(full, bi, m, 16);
                if (ov > bv || (ov == bv && oi < bi)) { bv = ov; bi = oi; }
            }
            if (a == 0) s_a[n] = bi;
        }
    }

    // ---------------- CSR adjacency build (deterministic, ascending e) ------
    {
        if (tid < NN) {
            int c = 0;
            for (int e = 0; e < EE; e++) if (s_et[e] == tid) c++;
            s_ino[tid + 1] = c;
        } else if (tid < 2 * NN) {
            int n = tid - NN; int c = 0;
            for (int e = 0; e < EE; e++) if (s_ef[e] == n) c++;
            s_out[n + 1] = c;
        }
        __syncthreads();
        if (tid == 0) {
            s_ino[0] = 0; s_out[0] = 0;
            for (int n = 0; n < NN; n++) {
                s_ino[n + 1] += s_ino[n];
                s_out[n + 1] += s_out[n];
            }
        }
        __syncthreads();
        if (tid < NN) {
            int c = s_ino[tid];
            for (int e = 0; e < EE; e++) if (s_et[e] == tid) s_inl[c++] = e;
        } else if (tid < 2 * NN) {
            int n = tid - NN; int c = s_out[n];
            for (int e = 0; e < EE; e++) if (s_ef[e] == n) s_onl[c++] = e;
        }
    }
    __syncthreads();

    // ---------------- eval helper ----------------
    auto do_eval = [&]() {
        float contrib = 0.f;
        if (tid < NN)
            contrib += s_nv[tid * AA + s_a[tid]] * (1.0f / NN);
        {
            int e  = tid;                        // 512 threads == EE
            int af = s_a[s_ef[e]];
            int at = s_a[s_et[e]];
            contrib += ldg_el1(&edge_vals[(((size_t)b * EE + e) * AA + af) * AA + at],
                               pol) * (1.0f / EE);
        }
        #pragma unroll
        for (int m = 16; m > 0; m >>= 1)
            contrib += __shfl_xor_sync(full, contrib, m);
        if (lane == 0) s_red[warp] = contrib;
        __syncthreads();
        if (warp == 0) {
            float v = (lane < 16) ? s_red[lane] : 0.f;
            #pragma unroll
            for (int m = 8; m > 0; m >>= 1)
                v += __shfl_xor_sync(full, v, m, 16);
            if (lane == 0) {
                if (v > sh_qmax) { sh_qmax = v; sh_flag = 1; }
                else             { sh_flag = 0; }
            }
        }
        __syncthreads();
        if (sh_flag && tid < NN) s_am[tid] = s_a[tid];
        __syncthreads();
    };

    do_eval();   // iteration-0 eval of raw argmax assignment

    const int tsel = lane >> 4;      // which of the warp's 2 concurrent tiles
    const int tl   = lane & 15;      // lane within tile
    const int rg   = tl >> 2;        // row group: rows 4*rg .. 4*rg+3
    const int kg   = tl & 3;         // col group: cols 4*kg .. 4*kg+3

    // ---------------- 8 message-passing iterations ----------------
    for (int it = 0; it < ITERS; it++) {
        // ---- message phase: 16 lanes per tile, 2 tiles per warp, 4x4 blocks ----
        {
            const float sc = 1.0f / EE;
            #pragma unroll 2
            for (int i = 0; i < 16; i++) {
                int e = (warp << 5) + (i << 1) + tsel;
                const float4* tile4 =
                    (const float4*)(edge_vals + (((size_t)b * EE + e) << 8));
                int nf = s_ef[e], nt = s_et[e];
                float* mfp = s_mf + (e << 4);
                float* mbp = s_mb + (e << 4);

                // d[at] = q[to][at] - mf_old[at]   (this lane's 4 cols, group kg)
                float4 qt4  = ((const float4*)(s_q + (nt << 4)))[kg];
                float4 mfo4 = ((const float4*)mfp)[kg];
                float4 d4 = make_float4(qt4.x - mfo4.x, qt4.y - mfo4.y,
                                        qt4.z - mfo4.z, qt4.w - mfo4.w);
                // c[af] = q[from][af] - mb_old[af] (this lane's 4 rows, group rg)
                float4 qf4  = ((const float4*)(s_q + (nf << 4)))[rg];
                float4 mbo4 = ((const float4*)mbp)[rg];
                float4 c4 = make_float4(qf4.x - mbo4.x, qf4.y - mbo4.y,
                                        qf4.z - mbo4.z, qf4.w - mbo4.w);

                float4 f4, m4, v;
                int base = (rg << 4) + kg;      // float4 index of (row 4rg, colgrp kg)

                // j = 0 : row 4rg+0
                v = ldg_el4(tile4 + base, pol);
                v.x *= sc; v.y *= sc; v.z *= sc; v.w *= sc;
                m4.x = fmaxf(fmaxf(d4.x + v.x, d4.y + v.y),
                             fmaxf(d4.z + v.z, d4.w + v.w));
                f4.x = c4.x + v.x; f4.y = c4.x + v.y;
                f4.z = c4.x + v.z; f4.w = c4.x + v.w;
                // j = 1 : row 4rg+1
                v = ldg_el4(tile4 + base + 4, pol);
                v.x *= sc; v.y *= sc; v.z *= sc; v.w *= sc;
                m4.y = fmaxf(fmaxf(d4.x + v.x, d4.y + v.y),
                             fmaxf(d4.z + v.z, d4.w + v.w));
                f4.x = fmaxf(f4.x, c4.y + v.x); f4.y = fmaxf(f4.y, c4.y + v.y);
                f4.z = fmaxf(f4.z, c4.y + v.z); f4.w = fmaxf(f4.w, c4.y + v.w);
                // j = 2 : row 4rg+2
                v = ldg_el4(tile4 + base + 8, pol);
                v.x *= sc; v.y *= sc; v.z *= sc; v.w *= sc;
                m4.z = fmaxf(fmaxf(d4.x + v.x, d4.y + v.y),
                             fmaxf(d4.z + v.z, d4.w + v.w));
                f4.x = fmaxf(f4.x, c4.z + v.x); f4.y = fmaxf(f4.y, c4.z + v.y);
                f4.z = fmaxf(f4.z, c4.z + v.z); f4.w = fmaxf(f4.w, c4.z + v.w);
                // j = 3 : row 4rg+3
                v = ldg_el4(tile4 + base + 12, pol);
                v.x *= sc; v.y *= sc; v.z *= sc; v.w *= sc;
                m4.w = fmaxf(fmaxf(d4.x + v.x, d4.y + v.y),
                             fmaxf(d4.z + v.z, d4.w + v.w));
                f4.x = fmaxf(f4.x, c4.w + v.x); f4.y = fmaxf(f4.y, c4.w + v.y);
                f4.z = fmaxf(f4.z, c4.w + v.z); f4.w = fmaxf(f4.w, c4.w + v.w);

                // reduce row-maxes (mb) over the 4 col-groups: xor 1, 2 (exact max)
                m4.x = fmaxf(m4.x, __shfl_xor_sync(full, m4.x, 1));
                m4.y = fmaxf(m4.y, __shfl_xor_sync(full, m4.y, 1));
                m4.z = fmaxf(m4.z, __shfl_xor_sync(full, m4.z, 1));
                m4.w = fmaxf(m4.w, __shfl_xor_sync(full, m4.w, 1));
                m4.x = fmaxf(m4.x, __shfl_xor_sync(full, m4.x, 2));
                m4.y = fmaxf(m4.y, __shfl_xor_sync(full, m4.y, 2));
                m4.z = fmaxf(m4.z, __shfl_xor_sync(full, m4.z, 2));
                m4.w = fmaxf(m4.w, __shfl_xor_sync(full, m4.w, 2));

                // reduce col-maxes (mf) over the 4 row-groups: xor 4, 8 (exact max)
                f4.x = fmaxf(f4.x, __shfl_xor_sync(full, f4.x, 4));
                f4.y = fmaxf(f4.y, __shfl_xor_sync(full, f4.y, 4));
                f4.z = fmaxf(f4.z, __shfl_xor_sync(full, f4.z, 4));
                f4.w = fmaxf(f4.w, __shfl_xor_sync(full, f4.w, 4));
                f4.x = fmaxf(f4.x, __shfl_xor_sync(full, f4.x, 8));
                f4.y = fmaxf(f4.y, __shfl_xor_sync(full, f4.y, 8));
                f4.z = fmaxf(f4.z, __shfl_xor_sync(full, f4.z, 8));
                f4.w = fmaxf(f4.w, __shfl_xor_sync(full, f4.w, 8));

                // mean-center mf over 16 'at' (serial 4 + xor1 + xor2)
                float s = f4.x + f4.y + f4.z + f4.w;
                s += __shfl_xor_sync(full, s, 1);
                s += __shfl_xor_sync(full, s, 2);
                s *= (1.0f / AA);
                f4.x -= s; f4.y -= s; f4.z -= s; f4.w -= s;

                // mean-center mb over 16 'af' — exact R6/R8 sum tree
                float4 t4;
                t4.x = m4.x + __shfl_xor_sync(full, m4.x, 8);
                t4.y = m4.y + __shfl_xor_sync(full, m4.y, 8);
                t4.z = m4.z + __shfl_xor_sync(full, m4.z, 8);
                t4.w = m4.w + __shfl_xor_sync(full, m4.w, 8);
                float sm = (t4.x + t4.y) + (t4.z + t4.w);
                sm += __shfl_xor_sync(full, sm, 4);
                sm *= (1.0f / AA);
                m4.x -= sm; m4.y -= sm; m4.z -= sm; m4.w -= sm;

                if (rg == 0) ((float4*)mfp)[kg] = f4;
                if (kg == 0) ((float4*)mbp)[rg] = m4;
            }
        }
        __syncthreads();

        // ---- node update + argmax (two passes of 32 nodes) ----
        {
            #pragma unroll
            for (int p = 0; p < 2; p++) {
                int n = (tid >> 4) + p * 32;
                int a = tid & 15;
                float v = s_nv[n * AA + a] * (1.0f / NN);
                int i0 = s_ino[n], i1 = s_ino[n + 1];
                for (int i = i0; i < i1; i++) v += s_mf[(s_inl[i] << 4) + a];
                int o0 = s_out[n], o1 = s_out[n + 1];
                for (int i = o0; i < o1; i++) v += s_mb[(s_onl[i] << 4) + a];
                s_q[n * AA + a] = v;

                float bv = v; int bi = a;
                #pragma unroll
                for (int m = 1; m < 16; m <<= 1) {
                    float ov = __shfl_xor_sync(full, bv, m, 16);
                    int   oi = __shfl_xor_sync(full, bi, m, 16);
                    if (ov > bv || (ov == bv && oi < bi)) { bv = ov; bi = oi; }
                }
                if (a == 0) s_a[n] = bi;
            }
        }
        __syncthreads();

        // ---- eval current assignment, keep best ----
        do_eval();
    }

    // ---------------- write results directly ----------------
    int tot = BB + BB * NN;
    if (out_size >= tot) {
        if (tid == 0) out[b] = sh_qmax;
        if (tid < NN) out[BB + b * NN + tid] = (float)s_am[tid];
    } else if (out_size == BB * NN) {
        if (tid < NN) out[b * NN + tid] = (float)s_am[tid];
    } else {
        if (tid == 0 && b < out_size) out[b] = sh_qmax;
    }
}

// ---------------- launch ----------------------------------------------------
extern "C" void kernel_launch(void* const* d_in, const int* in_sizes, int n_in,
                              void* d_out, int out_size) {
    const float* node_vals = (const float*)d_in[0];
    const float* edge_vals = (const float*)d_in[1];
    const int*   ef        = (const int*)d_in[2];
    const int*   et        = (const int*)d_in[3];
    float* out = (float*)d_out;

    cudaFuncSetAttribute(k_main, cudaFuncAttributeMaxDynamicSharedMemorySize,
                         SMEM_BYTES);

    k_main<<<BB, THREADS, SMEM_BYTES>>>(node_vals, edge_vals, ef, et,
                                        out, out_size);
}